// round 3
// baseline (speedup 1.0000x reference)
#include <cuda_runtime.h>

// ---------------------------------------------------------------------------
// EnhancedReconstructionLoss: 0.8*MSE + 0.2*(1 - mean(SSIM_map)), fused.
//
// s/d reformulation (s=x+y, d=x-y) -> 4 window sums (Ws,Wd,Wss,Wdd):
//   N1 = (Ws^2-Wd^2) + 162*C1          N2 = 9(Wss-Wdd) - (Ws^2-Wd^2) + 162*C2
//   D1 = (Ws^2+Wd^2) + 162*C1          D2 = 9(Wss+Wdd) - (Ws^2+Wd^2) + 162*C2
//   ssim = N1*N2 / (D1*D2 + 4*6561*eps)
//
// R3: 4 cols/lane (halved register window -> ~2x occupancy), 32-row strips
// (6.25% halo overhead), packed f32x2 math, single fused kernel with atomic
// finalize.
// ---------------------------------------------------------------------------

typedef unsigned long long u64;

#define IMW 512
#define IMH 512
#define NPLANES 96
#define RPW 32                    // rows per warp-task
#define STRIPS 16                 // 512 / 32
#define QCOLS 4                   // warp-columns across width (128 cols each)
#define WPB 4                     // warps per block
#define NBLOCKS (NPLANES * STRIPS * QCOLS / WPB)   // 1536
#define NTOTD 25165824.0          // 32*3*512*512

__device__ float g_mse_acc  = 0.f;
__device__ float g_ssim_acc = 0.f;
__device__ unsigned int g_cnt = 0u;

__device__ __forceinline__ u64 f2_pack(float lo, float hi) {
    u64 r; asm("mov.b64 %0, {%1, %2};" : "=l"(r) : "f"(lo), "f"(hi)); return r;
}
__device__ __forceinline__ void f2_unpack(u64 p, float& lo, float& hi) {
    asm("mov.b64 {%0, %1}, %2;" : "=f"(lo), "=f"(hi) : "l"(p));
}
__device__ __forceinline__ u64 f2_set(float v) { return f2_pack(v, v); }
__device__ __forceinline__ u64 add2(u64 a, u64 b) {
    u64 d; asm("add.rn.f32x2 %0, %1, %2;" : "=l"(d) : "l"(a), "l"(b)); return d;
}
__device__ __forceinline__ u64 mul2(u64 a, u64 b) {
    u64 d; asm("mul.rn.f32x2 %0, %1, %2;" : "=l"(d) : "l"(a), "l"(b)); return d;
}
__device__ __forceinline__ u64 fma2(u64 a, u64 b, u64 c) {
    u64 d; asm("fma.rn.f32x2 %0, %1, %2, %3;" : "=l"(d) : "l"(a), "l"(b), "l"(c)); return d;
}

// Horizontal 3-sum over 4 columns (2 packed u64). vH = this lane's halo value
// (left halo for lane 0, right halo for lane 31; zero at image edges).
__device__ __forceinline__ void hsum4(u64 v0, u64 v1, float vH, int lane,
                                      u64& H0, u64& H1) {
    float f0, f1, f2, f3;
    f2_unpack(v0, f0, f1);
    f2_unpack(v1, f2, f3);
    float up = __shfl_up_sync(0xffffffffu, f3, 1);
    float dn = __shfl_down_sync(0xffffffffu, f0, 1);
    float nl = (lane == 0)  ? vH : up;
    float nr = (lane == 31) ? vH : dn;
    u64 L0 = f2_pack(nl, f0);
    u64 L1 = f2_pack(f1, f2);
    u64 R1 = f2_pack(f3, nr);
    H0 = add2(add2(L0, v0), L1);   // (nl+f0+f1, f0+f1+f2)
    H1 = add2(add2(L1, v1), R1);   // (f1+f2+f3, f2+f3+nr)
}

__global__ void __launch_bounds__(128, 5)
loss_fused(const float* __restrict__ X, const float* __restrict__ Y,
           float* __restrict__ out) {
    const int w    = threadIdx.x >> 5;
    const int lane = threadIdx.x & 31;
    const int task  = blockIdx.x * WPB + w;
    const int qcol  = task & (QCOLS - 1);
    const int strip = (task >> 2) & (STRIPS - 1);
    const int plane = task >> 6;
    const int R0 = strip * RPW;
    const int c0 = qcol * 128 + (lane << 2);

    const float* px = X + (size_t)plane * (IMW * IMH) + c0;
    const float* py = Y + (size_t)plane * (IMW * IMH) + c0;

    const bool hval = (lane == 0) ? (qcol > 0)
                    : ((lane == 31) ? (qcol < QCOLS - 1) : false);
    const int hoff = (lane == 0) ? -1 : 4;

    const u64 km1  = f2_set(-1.0f);
    const u64 k9   = f2_set(9.0f);
    const u64 kC1  = f2_set(0.0162f);      // 162 * C1
    const u64 kC2  = f2_set(0.1458f);      // 162 * C2
    const u64 kEPS = f2_set(2.6244e-4f);   // 4 * 6561 * eps

    // 4-slot rolling window of s,d rows (4 cols = 2 u64 each) + halo scalars.
    u64 ws[4][2], wdv[4][2];
    float whs[4], whd[4];

    // Load input row gr = R0-1+j into slot j&3 (zeros outside the image).
    auto LOAD = [&](int j) {
        const int slot = j & 3;
        const int gr = R0 - 1 + j;
        const bool v = ((unsigned)gr < (unsigned)IMH);
        float4 xa = make_float4(0.f, 0.f, 0.f, 0.f), ya = xa;
        if (v) {
            xa = *reinterpret_cast<const float4*>(px + (size_t)gr * IMW);
            ya = *reinterpret_cast<const float4*>(py + (size_t)gr * IMW);
        }
        float hx = 0.f, hy = 0.f;
        if (v && hval) {
            hx = px[(size_t)gr * IMW + hoff];
            hy = py[(size_t)gr * IMW + hoff];
        }
        u64 xp0 = f2_pack(xa.x, xa.y), xp1 = f2_pack(xa.z, xa.w);
        u64 yp0 = f2_pack(ya.x, ya.y), yp1 = f2_pack(ya.z, ya.w);
        ws[slot][0] = add2(xp0, yp0);   wdv[slot][0] = fma2(yp0, km1, xp0);
        ws[slot][1] = add2(xp1, yp1);   wdv[slot][1] = fma2(yp1, km1, xp1);
        whs[slot] = hx + hy;
        whd[slot] = hx - hy;
    };

    LOAD(0); LOAD(1); LOAD(2);

    u64 mAcc0 = f2_set(0.f), mAcc1 = f2_set(0.f);
    float sAcc = 0.f;

#pragma unroll
    for (int r = 0; r < RPW; ++r) {
        if (r + 3 <= RPW + 1) LOAD(r + 3);   // prefetch next input row

        const int j0 = r & 3, j1 = (r + 1) & 3, j2 = (r + 2) & 3;

        // ---- vertical 3-sums ----
        u64 Vs[2], Vd[2], Vss[2], Vdd[2];
#pragma unroll
        for (int k = 0; k < 2; ++k) {
            u64 s0 = ws[j0][k], s1 = ws[j1][k], s2 = ws[j2][k];
            u64 d0 = wdv[j0][k], d1 = wdv[j1][k], d2 = wdv[j2][k];
            Vs[k]  = add2(add2(s0, s1), s2);
            Vd[k]  = add2(add2(d0, d1), d2);
            Vss[k] = fma2(s0, s0, fma2(s1, s1, mul2(s2, s2)));
            Vdd[k] = fma2(d0, d0, fma2(d1, d1, mul2(d2, d2)));
        }
        // halo vertical sums (consumed only by lanes 0/31)
        float hs0 = whs[j0], hs1 = whs[j1], hs2 = whs[j2];
        float hd0 = whd[j0], hd1 = whd[j1], hd2 = whd[j2];
        float vHs  = hs0 + hs1 + hs2;
        float vHd  = hd0 + hd1 + hd2;
        float vHss = fmaf(hs0, hs0, fmaf(hs1, hs1, hs2 * hs2));
        float vHdd = fmaf(hd0, hd0, fmaf(hd1, hd1, hd2 * hd2));

        // ---- horizontal 3-sums ----
        u64 Hs[2], Hdq[2], Hss[2], Hdd[2];
        hsum4(Vs[0],  Vs[1],  vHs,  lane, Hs[0],  Hs[1]);
        hsum4(Vd[0],  Vd[1],  vHd,  lane, Hdq[0], Hdq[1]);
        hsum4(Vss[0], Vss[1], vHss, lane, Hss[0], Hss[1]);
        hsum4(Vdd[0], Vdd[1], vHdd, lane, Hdd[0], Hdd[1]);

        // ---- SSIM rational per packed pair ----
#pragma unroll
        for (int k = 0; k < 2; ++k) {
            u64 E  = mul2(Hs[k], Hs[k]);
            u64 F  = mul2(Hdq[k], Hdq[k]);
            u64 T1 = fma2(F, km1, E);          // E - F
            u64 T2 = add2(E, F);
            u64 N1 = add2(T1, kC1);
            u64 D1 = add2(T2, kC1);
            u64 U1 = fma2(Hdd[k], km1, Hss[k]); // Wss - Wdd
            u64 U2 = add2(Hss[k], Hdd[k]);
            u64 N2 = fma2(T1, km1, fma2(U1, k9, kC2));
            u64 D2 = fma2(T2, km1, fma2(U2, k9, kC2));
            u64 num = mul2(N1, N2);
            u64 den = fma2(D1, D2, kEPS);
            float n0, n1, d0, d1;
            f2_unpack(num, n0, n1);
            f2_unpack(den, d0, d1);
            sAcc += __fdividef(n0, d0);
            sAcc += __fdividef(n1, d1);
        }

        // ---- MSE on the center row (input row R0+r = slot j1) ----
        mAcc0 = fma2(wdv[j1][0], wdv[j1][0], mAcc0);
        mAcc1 = fma2(wdv[j1][1], wdv[j1][1], mAcc1);
    }

    // ---- reductions ----
    float m0, m1, m2, m3;
    f2_unpack(mAcc0, m0, m1);
    f2_unpack(mAcc1, m2, m3);
    float mAcc = (m0 + m1) + (m2 + m3);
#pragma unroll
    for (int o = 16; o; o >>= 1) {
        mAcc += __shfl_xor_sync(0xffffffffu, mAcc, o);
        sAcc += __shfl_xor_sync(0xffffffffu, sAcc, o);
    }
    __shared__ float shm[WPB], shs[WPB];
    if (lane == 0) { shm[w] = mAcc; shs[w] = sAcc; }
    __syncthreads();
    if (threadIdx.x == 0) {
        float M = (shm[0] + shm[1]) + (shm[2] + shm[3]);
        float S = (shs[0] + shs[1]) + (shs[2] + shs[3]);
        atomicAdd(&g_mse_acc, M);
        atomicAdd(&g_ssim_acc, S);
        __threadfence();
        unsigned c = atomicInc(&g_cnt, NBLOCKS - 1);   // wraps to 0 on last
        if (c == NBLOCKS - 1) {
            __threadfence();
            float Mt = atomicExch(&g_mse_acc, 0.f);
            float St = atomicExch(&g_ssim_acc, 0.f);
            double mse  = (double)Mt / NTOTD;
            double ssim = (double)St / NTOTD;
            out[0] = (float)(0.8 * mse + 0.2 * (1.0 - ssim));
        }
    }
}

extern "C" void kernel_launch(void* const* d_in, const int* in_sizes, int n_in,
                              void* d_out, int out_size) {
    const float* X = (const float*)d_in[0];
    const float* Y = (const float*)d_in[1];
    loss_fused<<<NBLOCKS, 128>>>(X, Y, (float*)d_out);
}

// round 4
// speedup vs baseline: 1.1835x; 1.1835x over previous
#include <cuda_runtime.h>

// ---------------------------------------------------------------------------
// EnhancedReconstructionLoss: 0.8*MSE + 0.2*(1 - mean(SSIM_map)), fused.
//
// s/d reformulation (s=x+y, d=x-y) -> 4 window sums (Ws,Wd,Wss,Wdd):
//   N1 = (Ws^2-Wd^2) + 162*C1          N2 = 9(Wss-Wdd) - (Ws^2-Wd^2) + 162*C2
//   D1 = (Ws^2+Wd^2) + 162*C1          D2 = 9(Wss+Wdd) - (Ws^2+Wd^2) + 162*C2
//   ssim = N1*N2 / (D1*D2 + 4*6561*eps)
//
// R4: back to the efficient R2 layout (8 cols/lane, 16-row strips), but with
// a 3-slot rolling window and a register cap (launch_bounds 128,5) to double
// occupancy at constant instruction count.
// ---------------------------------------------------------------------------

typedef unsigned long long u64;

#define IMW 512
#define IMH 512
#define NPLANES 96
#define RPW 16                    // rows per warp-task
#define STRIPS 32                 // 512 / 16
#define WPB 4                     // warps per block
#define NBLOCKS (NPLANES * STRIPS * 2 / WPB)   // 1536
#define NTOTD 25165824.0          // 32*3*512*512

__device__ float g_mse_acc  = 0.f;
__device__ float g_ssim_acc = 0.f;
__device__ unsigned int g_cnt = 0u;

__device__ __forceinline__ u64 f2_pack(float lo, float hi) {
    u64 r; asm("mov.b64 %0, {%1, %2};" : "=l"(r) : "f"(lo), "f"(hi)); return r;
}
__device__ __forceinline__ void f2_unpack(u64 p, float& lo, float& hi) {
    asm("mov.b64 {%0, %1}, %2;" : "=f"(lo), "=f"(hi) : "l"(p));
}
__device__ __forceinline__ u64 f2_set(float v) { return f2_pack(v, v); }
__device__ __forceinline__ u64 add2(u64 a, u64 b) {
    u64 d; asm("add.rn.f32x2 %0, %1, %2;" : "=l"(d) : "l"(a), "l"(b)); return d;
}
__device__ __forceinline__ u64 mul2(u64 a, u64 b) {
    u64 d; asm("mul.rn.f32x2 %0, %1, %2;" : "=l"(d) : "l"(a), "l"(b)); return d;
}
__device__ __forceinline__ u64 fma2(u64 a, u64 b, u64 c) {
    u64 d; asm("fma.rn.f32x2 %0, %1, %2, %3;" : "=l"(d) : "l"(a), "l"(b), "l"(c)); return d;
}

// Horizontal 3-sum over 8 columns (4 packed u64), warp-shuffle neighbors plus
// scalar halo vH at the warp's interior boundary.
// half==0: cols [0,256) -> left edge is pad(0), right neighbor needs vH.
// half==1: cols [256,512) -> left needs vH, right edge is pad(0).
__device__ __forceinline__ void hsum8(const u64 v0, const u64 v1, const u64 v2, const u64 v3,
                                      float vH, int lane, int half,
                                      u64& H0, u64& H1, u64& H2, u64& H3) {
    float f0, f1, f2, f3, f4, f5, f6, f7;
    f2_unpack(v0, f0, f1);
    f2_unpack(v1, f2, f3);
    f2_unpack(v2, f4, f5);
    f2_unpack(v3, f6, f7);
    float up = __shfl_up_sync(0xffffffffu, f7, 1);
    float dn = __shfl_down_sync(0xffffffffu, f0, 1);
    float nl = (lane == 0)  ? (half ? vH : 0.f) : up;
    float nr = (lane == 31) ? (half ? 0.f : vH) : dn;
    u64 L0 = f2_pack(nl, f0);
    u64 L1 = f2_pack(f1, f2);
    u64 L2 = f2_pack(f3, f4);
    u64 L3 = f2_pack(f5, f6);
    u64 R3 = f2_pack(f7, nr);
    H0 = add2(add2(L0, v0), L1);
    H1 = add2(add2(L1, v1), L2);
    H2 = add2(add2(L2, v2), L3);
    H3 = add2(add2(L3, v3), R3);
}

__global__ void __launch_bounds__(128, 5)
loss_fused(const float* __restrict__ X, const float* __restrict__ Y,
           float* __restrict__ out) {
    const int w    = threadIdx.x >> 5;
    const int lane = threadIdx.x & 31;
    const int task  = blockIdx.x * WPB + w;
    const int half  = task & 1;
    const int strip = (task >> 1) & (STRIPS - 1);
    const int plane = task >> 6;
    const int R0 = strip * RPW;
    const int c0 = half * 256 + (lane << 3);

    const float* px = X + (size_t)plane * (IMW * IMH) + c0;
    const float* py = Y + (size_t)plane * (IMW * IMH) + c0;

    const bool hval = (lane == 0) ? (half == 1)
                    : ((lane == 31) ? (half == 0) : false);
    const int hoff = (lane == 0) ? -1 : 8;

    const u64 km1  = f2_set(-1.0f);
    const u64 k9   = f2_set(9.0f);
    const u64 kC1  = f2_set(0.0162f);      // 162 * C1
    const u64 kC2  = f2_set(0.1458f);      // 162 * C2
    const u64 kEPS = f2_set(2.6244e-4f);   // 4 * 6561 * eps

    // 3-slot rolling window of s,d rows (8 cols = 4 u64 each) + halo scalars.
    u64 ws[3][4], wdv[3][4];
    float whs[3], whd[3];

    // Load input row gr = R0-1+j into slot j%3 (zeros outside the image).
    auto LOAD = [&](int j) {
        const int slot = j % 3;
        const int gr = R0 - 1 + j;
        const bool v = ((unsigned)gr < (unsigned)IMH);
        float4 xa = make_float4(0.f, 0.f, 0.f, 0.f), xb = xa, ya = xa, yb = xa;
        if (v) {
            const float4* p4 = reinterpret_cast<const float4*>(px + (size_t)gr * IMW);
            const float4* q4 = reinterpret_cast<const float4*>(py + (size_t)gr * IMW);
            xa = p4[0]; xb = p4[1];
            ya = q4[0]; yb = q4[1];
        }
        float hx = 0.f, hy = 0.f;
        if (v && hval) {
            hx = px[(size_t)gr * IMW + hoff];
            hy = py[(size_t)gr * IMW + hoff];
        }
        u64 xp0 = f2_pack(xa.x, xa.y), xp1 = f2_pack(xa.z, xa.w);
        u64 xp2 = f2_pack(xb.x, xb.y), xp3 = f2_pack(xb.z, xb.w);
        u64 yp0 = f2_pack(ya.x, ya.y), yp1 = f2_pack(ya.z, ya.w);
        u64 yp2 = f2_pack(yb.x, yb.y), yp3 = f2_pack(yb.z, yb.w);
        ws[slot][0] = add2(xp0, yp0);   wdv[slot][0] = fma2(yp0, km1, xp0);
        ws[slot][1] = add2(xp1, yp1);   wdv[slot][1] = fma2(yp1, km1, xp1);
        ws[slot][2] = add2(xp2, yp2);   wdv[slot][2] = fma2(yp2, km1, xp2);
        ws[slot][3] = add2(xp3, yp3);   wdv[slot][3] = fma2(yp3, km1, xp3);
        whs[slot] = hx + hy;
        whd[slot] = hx - hy;
    };

    LOAD(0); LOAD(1);

    u64 mAcc0 = f2_set(0.f), mAcc1 = f2_set(0.f);
    float sAcc = 0.f;

#pragma unroll
    for (int r = 0; r < RPW; ++r) {
        LOAD(r + 2);   // row needed this iteration (r+2 <= 17 always in range check)

        const int j0 = r % 3, j1 = (r + 1) % 3, j2 = (r + 2) % 3;

        // halo vertical sums (consumed only by lanes 0/31)
        float hs0 = whs[j0], hs1 = whs[j1], hs2 = whs[j2];
        float hd0 = whd[j0], hd1 = whd[j1], hd2 = whd[j2];
        float vHs  = hs0 + hs1 + hs2;
        float vHd  = hd0 + hd1 + hd2;
        float vHss = fmaf(hs0, hs0, fmaf(hs1, hs1, hs2 * hs2));
        float vHdd = fmaf(hd0, hd0, fmaf(hd1, hd1, hd2 * hd2));

        // ---- Ws, Wd first; derive T1/T2/N1/D1; release Hs/Hd early ----
        u64 T1[4], T2[4];
        {
            u64 Vq[4], Hq[4];
#pragma unroll
            for (int k = 0; k < 4; ++k)
                Vq[k] = add2(add2(ws[j0][k], ws[j1][k]), ws[j2][k]);
            hsum8(Vq[0], Vq[1], Vq[2], Vq[3], vHs, lane, half,
                  Hq[0], Hq[1], Hq[2], Hq[3]);
            u64 Es[4];
#pragma unroll
            for (int k = 0; k < 4; ++k) Es[k] = mul2(Hq[k], Hq[k]);   // Ws^2
#pragma unroll
            for (int k = 0; k < 4; ++k)
                Vq[k] = add2(add2(wdv[j0][k], wdv[j1][k]), wdv[j2][k]);
            hsum8(Vq[0], Vq[1], Vq[2], Vq[3], vHd, lane, half,
                  Hq[0], Hq[1], Hq[2], Hq[3]);
#pragma unroll
            for (int k = 0; k < 4; ++k) {
                u64 F = mul2(Hq[k], Hq[k]);            // Wd^2
                T1[k] = fma2(F, km1, Es[k]);           // Ws^2 - Wd^2
                T2[k] = add2(Es[k], F);                // Ws^2 + Wd^2
            }
        }

        // ---- Wss, Wdd; finish the rational ----
        {
            u64 Vss[4], Vdd[4], Hss[4], Hdd[4];
#pragma unroll
            for (int k = 0; k < 4; ++k) {
                u64 s0 = ws[j0][k], s1 = ws[j1][k], s2 = ws[j2][k];
                u64 d0 = wdv[j0][k], d1 = wdv[j1][k], d2 = wdv[j2][k];
                Vss[k] = fma2(s0, s0, fma2(s1, s1, mul2(s2, s2)));
                Vdd[k] = fma2(d0, d0, fma2(d1, d1, mul2(d2, d2)));
            }
            hsum8(Vss[0], Vss[1], Vss[2], Vss[3], vHss, lane, half,
                  Hss[0], Hss[1], Hss[2], Hss[3]);
            hsum8(Vdd[0], Vdd[1], Vdd[2], Vdd[3], vHdd, lane, half,
                  Hdd[0], Hdd[1], Hdd[2], Hdd[3]);
#pragma unroll
            for (int k = 0; k < 4; ++k) {
                u64 N1 = add2(T1[k], kC1);
                u64 D1 = add2(T2[k], kC1);
                u64 U1 = fma2(Hdd[k], km1, Hss[k]);    // Wss - Wdd
                u64 U2 = add2(Hss[k], Hdd[k]);
                u64 N2 = fma2(T1[k], km1, fma2(U1, k9, kC2));
                u64 D2 = fma2(T2[k], km1, fma2(U2, k9, kC2));
                u64 num = mul2(N1, N2);
                u64 den = fma2(D1, D2, kEPS);
                float n0, n1, d0, d1;
                f2_unpack(num, n0, n1);
                f2_unpack(den, d0, d1);
                sAcc += __fdividef(n0, d0);
                sAcc += __fdividef(n1, d1);
            }
        }

        // ---- MSE on the center row (input row R0+r = slot j1) ----
        mAcc0 = fma2(wdv[j1][0], wdv[j1][0], mAcc0);
        mAcc0 = fma2(wdv[j1][1], wdv[j1][1], mAcc0);
        mAcc1 = fma2(wdv[j1][2], wdv[j1][2], mAcc1);
        mAcc1 = fma2(wdv[j1][3], wdv[j1][3], mAcc1);
    }

    // ---- reductions ----
    float m0, m1, m2, m3;
    f2_unpack(mAcc0, m0, m1);
    f2_unpack(mAcc1, m2, m3);
    float mAcc = (m0 + m1) + (m2 + m3);
#pragma unroll
    for (int o = 16; o; o >>= 1) {
        mAcc += __shfl_xor_sync(0xffffffffu, mAcc, o);
        sAcc += __shfl_xor_sync(0xffffffffu, sAcc, o);
    }
    __shared__ float shm[WPB], shs[WPB];
    if (lane == 0) { shm[w] = mAcc; shs[w] = sAcc; }
    __syncthreads();
    if (threadIdx.x == 0) {
        float M = (shm[0] + shm[1]) + (shm[2] + shm[3]);
        float S = (shs[0] + shs[1]) + (shs[2] + shs[3]);
        atomicAdd(&g_mse_acc, M);
        atomicAdd(&g_ssim_acc, S);
        __threadfence();
        unsigned c = atomicInc(&g_cnt, NBLOCKS - 1);   // wraps to 0 on last
        if (c == NBLOCKS - 1) {
            __threadfence();
            float Mt = atomicExch(&g_mse_acc, 0.f);
            float St = atomicExch(&g_ssim_acc, 0.f);
            double mse  = (double)Mt / NTOTD;
            double ssim = (double)St / NTOTD;
            out[0] = (float)(0.8 * mse + 0.2 * (1.0 - ssim));
        }
    }
}

extern "C" void kernel_launch(void* const* d_in, const int* in_sizes, int n_in,
                              void* d_out, int out_size) {
    const float* X = (const float*)d_in[0];
    const float* Y = (const float*)d_in[1];
    loss_fused<<<NBLOCKS, 128>>>(X, Y, (float*)d_out);
}

// round 5
// speedup vs baseline: 1.2459x; 1.0527x over previous
#include <cuda_runtime.h>

// ---------------------------------------------------------------------------
// EnhancedReconstructionLoss: 0.8*MSE + 0.2*(1 - mean(SSIM_map)), fused.
//
// s/d reformulation (s=x+y, d=x-y) -> 4 window sums (Ws,Wd,Wss,Wdd):
//   N1 = (Ws^2-Wd^2) + 162*C1          N2 = 9(Wss-Wdd) - (Ws^2-Wd^2) + 162*C2
//   D1 = (Ws^2+Wd^2) + 162*C1          D2 = 9(Wss+Wdd) - (Ws^2+Wd^2) + 162*C2
//   ssim = N1*N2 / (D1*D2 + 4*6561*eps)
//
// R5: R4 body (3-slot rolling window, lean transients) + distance-1 raw
// prefetch buffer so LDG latency is hidden behind a full iteration of
// compute. launch_bounds(128,4).
// ---------------------------------------------------------------------------

typedef unsigned long long u64;

#define IMW 512
#define IMH 512
#define NPLANES 96
#define RPW 16                    // rows per warp-task
#define STRIPS 32                 // 512 / 16
#define WPB 4                     // warps per block
#define NBLOCKS (NPLANES * STRIPS * 2 / WPB)   // 1536
#define NTOTD 25165824.0          // 32*3*512*512

__device__ float g_mse_acc  = 0.f;
__device__ float g_ssim_acc = 0.f;
__device__ unsigned int g_cnt = 0u;

__device__ __forceinline__ u64 f2_pack(float lo, float hi) {
    u64 r; asm("mov.b64 %0, {%1, %2};" : "=l"(r) : "f"(lo), "f"(hi)); return r;
}
__device__ __forceinline__ void f2_unpack(u64 p, float& lo, float& hi) {
    asm("mov.b64 {%0, %1}, %2;" : "=f"(lo), "=f"(hi) : "l"(p));
}
__device__ __forceinline__ u64 f2_set(float v) { return f2_pack(v, v); }
__device__ __forceinline__ u64 add2(u64 a, u64 b) {
    u64 d; asm("add.rn.f32x2 %0, %1, %2;" : "=l"(d) : "l"(a), "l"(b)); return d;
}
__device__ __forceinline__ u64 mul2(u64 a, u64 b) {
    u64 d; asm("mul.rn.f32x2 %0, %1, %2;" : "=l"(d) : "l"(a), "l"(b)); return d;
}
__device__ __forceinline__ u64 fma2(u64 a, u64 b, u64 c) {
    u64 d; asm("fma.rn.f32x2 %0, %1, %2, %3;" : "=l"(d) : "l"(a), "l"(b), "l"(c)); return d;
}

// Horizontal 3-sum over 8 columns (4 packed u64), warp-shuffle neighbors plus
// scalar halo vH at the warp's interior boundary.
// half==0: cols [0,256) -> left edge is pad(0), right neighbor needs vH.
// half==1: cols [256,512) -> left needs vH, right edge is pad(0).
__device__ __forceinline__ void hsum8(const u64 v0, const u64 v1, const u64 v2, const u64 v3,
                                      float vH, int lane, int half,
                                      u64& H0, u64& H1, u64& H2, u64& H3) {
    float f0, f1, f2, f3, f4, f5, f6, f7;
    f2_unpack(v0, f0, f1);
    f2_unpack(v1, f2, f3);
    f2_unpack(v2, f4, f5);
    f2_unpack(v3, f6, f7);
    float up = __shfl_up_sync(0xffffffffu, f7, 1);
    float dn = __shfl_down_sync(0xffffffffu, f0, 1);
    float nl = (lane == 0)  ? (half ? vH : 0.f) : up;
    float nr = (lane == 31) ? (half ? 0.f : vH) : dn;
    u64 L0 = f2_pack(nl, f0);
    u64 L1 = f2_pack(f1, f2);
    u64 L2 = f2_pack(f3, f4);
    u64 L3 = f2_pack(f5, f6);
    u64 R3 = f2_pack(f7, nr);
    H0 = add2(add2(L0, v0), L1);
    H1 = add2(add2(L1, v1), L2);
    H2 = add2(add2(L2, v2), L3);
    H3 = add2(add2(L3, v3), R3);
}

__global__ void __launch_bounds__(128, 4)
loss_fused(const float* __restrict__ X, const float* __restrict__ Y,
           float* __restrict__ out) {
    const int w    = threadIdx.x >> 5;
    const int lane = threadIdx.x & 31;
    const int task  = blockIdx.x * WPB + w;
    const int half  = task & 1;
    const int strip = (task >> 1) & (STRIPS - 1);
    const int plane = task >> 6;
    const int R0 = strip * RPW;
    const int c0 = half * 256 + (lane << 3);

    const float* px = X + (size_t)plane * (IMW * IMH) + c0;
    const float* py = Y + (size_t)plane * (IMW * IMH) + c0;

    const bool hval = (lane == 0) ? (half == 1)
                    : ((lane == 31) ? (half == 0) : false);
    const int hoff = (lane == 0) ? -1 : 8;

    const u64 km1  = f2_set(-1.0f);
    const u64 k9   = f2_set(9.0f);
    const u64 kC1  = f2_set(0.0162f);      // 162 * C1
    const u64 kC2  = f2_set(0.1458f);      // 162 * C2
    const u64 kEPS = f2_set(2.6244e-4f);   // 4 * 6561 * eps

    // 3-slot rolling window of s,d rows (8 cols = 4 u64 each) + halo scalars.
    u64 ws[3][4], wdv[3][4];
    float whs[3], whd[3];

    // Distance-1 prefetch buffer (raw loads for the NEXT window row).
    float4 pxa, pxb, pya, pyb;
    float phx, phy;

    // Issue loads of input row gr = R0-1+j into the prefetch buffer.
    auto PREFETCH = [&](int j) {
        const int gr = R0 - 1 + j;
        const bool v = ((unsigned)gr < (unsigned)IMH);
        pxa = make_float4(0.f, 0.f, 0.f, 0.f); pxb = pxa; pya = pxa; pyb = pxa;
        phx = 0.f; phy = 0.f;
        if (v) {
            const float4* p4 = reinterpret_cast<const float4*>(px + (size_t)gr * IMW);
            const float4* q4 = reinterpret_cast<const float4*>(py + (size_t)gr * IMW);
            pxa = p4[0]; pxb = p4[1];
            pya = q4[0]; pyb = q4[1];
            if (hval) {
                phx = px[(size_t)gr * IMW + hoff];
                phy = py[(size_t)gr * IMW + hoff];
            }
        }
    };

    // Convert the prefetch buffer into window slot j%3.
    auto CONVERT = [&](int j) {
        const int slot = j % 3;
        u64 xp0 = f2_pack(pxa.x, pxa.y), xp1 = f2_pack(pxa.z, pxa.w);
        u64 xp2 = f2_pack(pxb.x, pxb.y), xp3 = f2_pack(pxb.z, pxb.w);
        u64 yp0 = f2_pack(pya.x, pya.y), yp1 = f2_pack(pya.z, pya.w);
        u64 yp2 = f2_pack(pyb.x, pyb.y), yp3 = f2_pack(pyb.z, pyb.w);
        ws[slot][0] = add2(xp0, yp0);   wdv[slot][0] = fma2(yp0, km1, xp0);
        ws[slot][1] = add2(xp1, yp1);   wdv[slot][1] = fma2(yp1, km1, xp1);
        ws[slot][2] = add2(xp2, yp2);   wdv[slot][2] = fma2(yp2, km1, xp2);
        ws[slot][3] = add2(xp3, yp3);   wdv[slot][3] = fma2(yp3, km1, xp3);
        whs[slot] = phx + phy;
        whd[slot] = phx - phy;
    };

    PREFETCH(0); CONVERT(0);
    PREFETCH(1); CONVERT(1);
    PREFETCH(2);                       // row 2 in flight entering the loop

    u64 mAcc0 = f2_set(0.f), mAcc1 = f2_set(0.f);
    float sAcc = 0.f;

#pragma unroll
    for (int r = 0; r < RPW; ++r) {
        CONVERT(r + 2);                     // consume prefetched row
        if (r < RPW - 1) PREFETCH(r + 3);   // issue next row's loads

        const int j0 = r % 3, j1 = (r + 1) % 3, j2 = (r + 2) % 3;

        // halo vertical sums (consumed only by lanes 0/31)
        float hs0 = whs[j0], hs1 = whs[j1], hs2 = whs[j2];
        float hd0 = whd[j0], hd1 = whd[j1], hd2 = whd[j2];
        float vHs  = hs0 + hs1 + hs2;
        float vHd  = hd0 + hd1 + hd2;
        float vHss = fmaf(hs0, hs0, fmaf(hs1, hs1, hs2 * hs2));
        float vHdd = fmaf(hd0, hd0, fmaf(hd1, hd1, hd2 * hd2));

        // ---- Ws, Wd first; derive T1/T2; release transients early ----
        u64 T1[4], T2[4];
        {
            u64 Vq[4], Hq[4];
#pragma unroll
            for (int k = 0; k < 4; ++k)
                Vq[k] = add2(add2(ws[j0][k], ws[j1][k]), ws[j2][k]);
            hsum8(Vq[0], Vq[1], Vq[2], Vq[3], vHs, lane, half,
                  Hq[0], Hq[1], Hq[2], Hq[3]);
            u64 Es[4];
#pragma unroll
            for (int k = 0; k < 4; ++k) Es[k] = mul2(Hq[k], Hq[k]);   // Ws^2
#pragma unroll
            for (int k = 0; k < 4; ++k)
                Vq[k] = add2(add2(wdv[j0][k], wdv[j1][k]), wdv[j2][k]);
            hsum8(Vq[0], Vq[1], Vq[2], Vq[3], vHd, lane, half,
                  Hq[0], Hq[1], Hq[2], Hq[3]);
#pragma unroll
            for (int k = 0; k < 4; ++k) {
                u64 F = mul2(Hq[k], Hq[k]);            // Wd^2
                T1[k] = fma2(F, km1, Es[k]);           // Ws^2 - Wd^2
                T2[k] = add2(Es[k], F);                // Ws^2 + Wd^2
            }
        }

        // ---- Wss, Wdd; finish the rational ----
        {
            u64 Vss[4], Vdd[4], Hss[4], Hdd[4];
#pragma unroll
            for (int k = 0; k < 4; ++k) {
                u64 s0 = ws[j0][k], s1 = ws[j1][k], s2 = ws[j2][k];
                u64 d0 = wdv[j0][k], d1 = wdv[j1][k], d2 = wdv[j2][k];
                Vss[k] = fma2(s0, s0, fma2(s1, s1, mul2(s2, s2)));
                Vdd[k] = fma2(d0, d0, fma2(d1, d1, mul2(d2, d2)));
            }
            hsum8(Vss[0], Vss[1], Vss[2], Vss[3], vHss, lane, half,
                  Hss[0], Hss[1], Hss[2], Hss[3]);
            hsum8(Vdd[0], Vdd[1], Vdd[2], Vdd[3], vHdd, lane, half,
                  Hdd[0], Hdd[1], Hdd[2], Hdd[3]);
#pragma unroll
            for (int k = 0; k < 4; ++k) {
                u64 N1 = add2(T1[k], kC1);
                u64 D1 = add2(T2[k], kC1);
                u64 U1 = fma2(Hdd[k], km1, Hss[k]);    // Wss - Wdd
                u64 U2 = add2(Hss[k], Hdd[k]);
                u64 N2 = fma2(T1[k], km1, fma2(U1, k9, kC2));
                u64 D2 = fma2(T2[k], km1, fma2(U2, k9, kC2));
                u64 num = mul2(N1, N2);
                u64 den = fma2(D1, D2, kEPS);
                float n0, n1, d0, d1;
                f2_unpack(num, n0, n1);
                f2_unpack(den, d0, d1);
                sAcc += __fdividef(n0, d0);
                sAcc += __fdividef(n1, d1);
            }
        }

        // ---- MSE on the center row (input row R0+r = slot j1) ----
        mAcc0 = fma2(wdv[j1][0], wdv[j1][0], mAcc0);
        mAcc0 = fma2(wdv[j1][1], wdv[j1][1], mAcc0);
        mAcc1 = fma2(wdv[j1][2], wdv[j1][2], mAcc1);
        mAcc1 = fma2(wdv[j1][3], wdv[j1][3], mAcc1);
    }

    // ---- reductions ----
    float m0, m1, m2, m3;
    f2_unpack(mAcc0, m0, m1);
    f2_unpack(mAcc1, m2, m3);
    float mAcc = (m0 + m1) + (m2 + m3);
#pragma unroll
    for (int o = 16; o; o >>= 1) {
        mAcc += __shfl_xor_sync(0xffffffffu, mAcc, o);
        sAcc += __shfl_xor_sync(0xffffffffu, sAcc, o);
    }
    __shared__ float shm[WPB], shs[WPB];
    if (lane == 0) { shm[w] = mAcc; shs[w] = sAcc; }
    __syncthreads();
    if (threadIdx.x == 0) {
        float M = (shm[0] + shm[1]) + (shm[2] + shm[3]);
        float S = (shs[0] + shs[1]) + (shs[2] + shs[3]);
        atomicAdd(&g_mse_acc, M);
        atomicAdd(&g_ssim_acc, S);
        __threadfence();
        unsigned c = atomicInc(&g_cnt, NBLOCKS - 1);   // wraps to 0 on last
        if (c == NBLOCKS - 1) {
            __threadfence();
            float Mt = atomicExch(&g_mse_acc, 0.f);
            float St = atomicExch(&g_ssim_acc, 0.f);
            double mse  = (double)Mt / NTOTD;
            double ssim = (double)St / NTOTD;
            out[0] = (float)(0.8 * mse + 0.2 * (1.0 - ssim));
        }
    }
}

extern "C" void kernel_launch(void* const* d_in, const int* in_sizes, int n_in,
                              void* d_out, int out_size) {
    const float* X = (const float*)d_in[0];
    const float* Y = (const float*)d_in[1];
    loss_fused<<<NBLOCKS, 128>>>(X, Y, (float*)d_out);
}